// round 5
// baseline (speedup 1.0000x reference)
#include <cuda_runtime.h>

#define Bv 4
#define Tv 256
#define Ev 512
#define Hv 8
#define Sv 64

// scratch (allocation-free rule: __device__ globals)
__device__ float g_q[Bv*Tv*Ev];
__device__ float g_k[Bv*Tv*Ev];
__device__ float g_v[Bv*Tv*Ev];
__device__ float g_scc[Bv*Hv*Tv*Tv];   // [b][n][i][j]; scc, then reused as prob
__device__ float g_vec[Bv*Tv*Ev];

// ---------------------------------------------------------------------------
// K1: per-token q/k/v projections.
// ---------------------------------------------------------------------------
__global__ void __launch_bounds__(256) qkv_kernel(const float* __restrict__ x,
                                                  const float* __restrict__ Wq,
                                                  const float* __restrict__ Wk,
                                                  const float* __restrict__ Wv)
{
    __shared__ float Ws[64][65];
    __shared__ float xs[Ev];
    const int bt  = blockIdx.x;
    const int tid = threadIdx.x;

    xs[tid]       = x[(size_t)bt*Ev + tid];
    xs[tid + 256] = x[(size_t)bt*Ev + tid + 256];

    const float* Wlist[3] = {Wq, Wk, Wv};
    float*       Olist[3] = {g_q, g_k, g_v};

    #pragma unroll
    for (int w = 0; w < 3; w++) {
        __syncthreads();
        const float* W = Wlist[w];
        for (int idx = tid; idx < 64*64; idx += 256)
            Ws[idx >> 6][idx & 63] = W[idx];
        __syncthreads();

        const int e0 = 2 * tid;
        const int n  = e0 >> 6;
        const int o0 = e0 & 63;
        const float* xr = &xs[n * 64];
        float a0 = 0.f, a1 = 0.f;
        #pragma unroll
        for (int d = 0; d < 64; d++) {
            const float xv = xr[d];
            a0 = fmaf(xv, Ws[o0][d],     a0);
            a1 = fmaf(xv, Ws[o0 + 1][d], a1);
        }
        Olist[w][(size_t)bt*Ev + e0]     = a0;
        Olist[w][(size_t)bt*Ev + e0 + 1] = a1;
    }
}

// ---------------------------------------------------------------------------
// K2: content-content scores  scc[b][n][i][j] = sum_d q[b,i,n,d]*k[b,j,n,d]
// ---------------------------------------------------------------------------
__global__ void __launch_bounds__(256) scc_kernel()
{
    __shared__ float qs[64][65];
    __shared__ float ks[64][65];
    const int it = blockIdx.x * 64;
    const int jt = blockIdx.y * 64;
    const int b  = blockIdx.z >> 3;
    const int n  = blockIdx.z & 7;
    const int tid = threadIdx.x;

    for (int idx = tid; idx < 4096; idx += 256) {
        const int r = idx >> 6, d = idx & 63;
        qs[r][d] = g_q[(((size_t)b*Tv + it + r)*Hv + n)*Sv + d];
        ks[r][d] = g_k[(((size_t)b*Tv + jt + r)*Hv + n)*Sv + d];
    }
    __syncthreads();

    const int ty = tid >> 4, tx = tid & 15;
    float acc[4][4] = {};
    #pragma unroll 8
    for (int d = 0; d < 64; d++) {
        float a[4], c[4];
        #pragma unroll
        for (int r = 0; r < 4; r++) a[r] = qs[ty*4 + r][d];
        #pragma unroll
        for (int cc = 0; cc < 4; cc++) c[cc] = ks[tx*4 + cc][d];
        #pragma unroll
        for (int r = 0; r < 4; r++)
            #pragma unroll
            for (int cc = 0; cc < 4; cc++)
                acc[r][cc] = fmaf(a[r], c[cc], acc[r][cc]);
    }

    #pragma unroll
    for (int r = 0; r < 4; r++)
        #pragma unroll
        for (int cc = 0; cc < 4; cc++)
            g_scc[(((size_t)b*Hv + n)*Tv + it + ty*4 + r)*Tv + jt + tx*4 + cc] = acc[r][cc];
}

// ---------------------------------------------------------------------------
// K3: streaming attention. Pass B now streams ONLY ev; prob stored to g_scc
// (overwrites consumed scc) for the pv GEMM.
// ---------------------------------------------------------------------------
__global__ void __launch_bounds__(256) attn_kernel(const float* __restrict__ ek,
                                                   const float* __restrict__ ev,
                                                   const int*   __restrict__ mask)
{
    __shared__ float sc[Hv][Tv];     // scores -> probs
    __shared__ float qsm[Ev];

    const int bi   = blockIdx.x;
    const int b    = bi >> 8;
    const int i    = bi & 255;
    const int tid  = threadIdx.x;
    const int warp = tid >> 5;
    const int lane = tid & 31;

    qsm[tid]       = g_q[(size_t)bi*Ev + tid];
    qsm[tid + 256] = g_q[(size_t)bi*Ev + tid + 256];

    // preload content-content scores: sc[n][j]
    #pragma unroll
    for (int t = 0; t < 8; t++)
        sc[t][tid] = g_scc[(((size_t)b*Hv + t)*Tv + i)*Tv + tid];
    __syncthreads();

    const float q0 = qsm[warp*64 + 2*lane];
    const float q1 = qsm[warp*64 + 2*lane + 1];

    const float2* ekp = (const float2*)ek + (((size_t)bi*Tv*Ev) >> 1) + warp*32 + lane;

    // ---- Pass A: stream ek, add q.ek to scores ----
    for (int j0 = 0; j0 < Tv; j0 += 8) {
        float2 r[8];
        #pragma unroll
        for (int u = 0; u < 8; u++) r[u] = ekp[(size_t)(j0 + u) * 256];
        #pragma unroll
        for (int u = 0; u < 8; u++) {
            float p = fmaf(r[u].x, q0, r[u].y * q1);
            p += __shfl_xor_sync(0xffffffffu, p, 16);
            p += __shfl_xor_sync(0xffffffffu, p, 8);
            p += __shfl_xor_sync(0xffffffffu, p, 4);
            p += __shfl_xor_sync(0xffffffffu, p, 2);
            p += __shfl_xor_sync(0xffffffffu, p, 1);
            if (lane == 0) sc[warp][j0 + u] += p;
        }
    }
    __syncwarp();

    // ---- softmax per head (warp-local over 256 j) ----
    const float scale = 0.125f;   // 1/sqrt(64)
    const int* mrow = mask + (size_t)bi * Tv;
    float vbuf[8];
    float mx = -1e30f;
    #pragma unroll
    for (int t = 0; t < 8; t++) {
        const int j = lane + 32*t;
        float s = sc[warp][j];
        s = (mrow[j] == 0) ? -1e9f : s * scale;
        vbuf[t] = s;
        mx = fmaxf(mx, s);
    }
    mx = fmaxf(mx, __shfl_xor_sync(0xffffffffu, mx, 16));
    mx = fmaxf(mx, __shfl_xor_sync(0xffffffffu, mx, 8));
    mx = fmaxf(mx, __shfl_xor_sync(0xffffffffu, mx, 4));
    mx = fmaxf(mx, __shfl_xor_sync(0xffffffffu, mx, 2));
    mx = fmaxf(mx, __shfl_xor_sync(0xffffffffu, mx, 1));
    float sum = 0.f;
    #pragma unroll
    for (int t = 0; t < 8; t++) {
        const float e = expf(vbuf[t] - mx);
        vbuf[t] = e;
        sum += e;
    }
    sum += __shfl_xor_sync(0xffffffffu, sum, 16);
    sum += __shfl_xor_sync(0xffffffffu, sum, 8);
    sum += __shfl_xor_sync(0xffffffffu, sum, 4);
    sum += __shfl_xor_sync(0xffffffffu, sum, 2);
    sum += __shfl_xor_sync(0xffffffffu, sum, 1);
    const float inv = 1.f / sum;
    float* prow = &g_scc[(((size_t)b*Hv + warp)*Tv + i)*Tv];
    #pragma unroll
    for (int t = 0; t < 8; t++) {
        const float p = vbuf[t] * inv;
        sc[warp][lane + 32*t] = p;
        prow[lane + 32*t] = p;           // prob -> gmem for pv GEMM
    }
    __syncwarp();

    // ---- Pass B: stream ev only ----
    const float2* evp = (const float2*)ev + (((size_t)bi*Tv*Ev) >> 1) + warp*32 + lane;
    float a0 = 0.f, a1 = 0.f;
    for (int j0 = 0; j0 < Tv; j0 += 8) {
        float2 re[8];
        #pragma unroll
        for (int u = 0; u < 8; u++) re[u] = evp[(size_t)(j0 + u) * 256];
        #pragma unroll
        for (int u = 0; u < 8; u++) {
            const float p = sc[warp][j0 + u];
            a0 = fmaf(p, re[u].x, a0);
            a1 = fmaf(p, re[u].y, a1);
        }
    }
    g_vec[(size_t)bi*Ev + warp*64 + 2*lane]     = a0;
    g_vec[(size_t)bi*Ev + warp*64 + 2*lane + 1] = a1;
}

// ---------------------------------------------------------------------------
// K3b: pv GEMM.  vec[b,i,n,d] += sum_j prob[b,n,i,j] * v[b,j,n,d]
// grid = (4 i-tiles, 32 b*n), 256 threads, 64x64 tiles, K=256 in 64-chunks.
// ---------------------------------------------------------------------------
__global__ void __launch_bounds__(256) pv_kernel()
{
    __shared__ float ps[64][65];   // prob tile [i][j]
    __shared__ float vs[64][65];   // v tile    [j][d]
    const int it = blockIdx.x * 64;
    const int b  = blockIdx.y >> 3;
    const int n  = blockIdx.y & 7;
    const int tid = threadIdx.x;
    const int ty = tid >> 4, tx = tid & 15;

    float acc[4][4] = {};

    for (int j0 = 0; j0 < Tv; j0 += 64) {
        __syncthreads();
        for (int idx = tid; idx < 4096; idx += 256) {
            const int r = idx >> 6, c = idx & 63;
            ps[r][c] = g_scc[(((size_t)b*Hv + n)*Tv + it + r)*Tv + j0 + c];
            vs[r][c] = g_v[(((size_t)b*Tv + j0 + r)*Hv + n)*Sv + c];
        }
        __syncthreads();

        #pragma unroll 8
        for (int j = 0; j < 64; j++) {
            float a[4], c[4];
            #pragma unroll
            for (int r = 0; r < 4; r++) a[r] = ps[ty*4 + r][j];
            #pragma unroll
            for (int cc = 0; cc < 4; cc++) c[cc] = vs[j][tx*4 + cc];
            #pragma unroll
            for (int r = 0; r < 4; r++)
                #pragma unroll
                for (int cc = 0; cc < 4; cc++)
                    acc[r][cc] = fmaf(a[r], c[cc], acc[r][cc]);
        }
    }

    #pragma unroll
    for (int r = 0; r < 4; r++)
        #pragma unroll
        for (int cc = 0; cc < 4; cc++) {
            const size_t o = (((size_t)b*Tv + it + ty*4 + r)*Hv + n)*Sv + tx*4 + cc;
            g_vec[o] += acc[r][cc];
        }
}

// ---------------------------------------------------------------------------
// K4: out = vec @ Wu^T + bu.  BM=BN=BK=32, grid (32,16)=512 CTAs, 128 thr.
// ---------------------------------------------------------------------------
__global__ void __launch_bounds__(128) proj_kernel(const float* __restrict__ Wu,
                                                   const float* __restrict__ bu,
                                                   float* __restrict__ out)
{
    __shared__ float As[32][36];   // [k][r]
    __shared__ float Bs[32][36];   // [k][c]
    const int r0  = blockIdx.x * 32;
    const int c0  = blockIdx.y * 32;
    const int tid = threadIdx.x;
    const int ty  = tid >> 4;       // 0..7  -> rows ty*4..+3
    const int tx  = tid & 15;       // 0..15 -> cols tx*2..+1

    float acc[4][2] = {};

    for (int k0 = 0; k0 < Ev; k0 += 32) {
        __syncthreads();
        #pragma unroll
        for (int ch = tid; ch < 256; ch += 128) {
            const int r = ch >> 3, k = (ch & 7) * 4;
            const float4 v4 = *(const float4*)&g_vec[(size_t)(r0 + r)*Ev + k0 + k];
            As[k][r] = v4.x; As[k+1][r] = v4.y; As[k+2][r] = v4.z; As[k+3][r] = v4.w;
        }
        #pragma unroll
        for (int ch = tid; ch < 256; ch += 128) {
            const int c = ch >> 3, k = (ch & 7) * 4;
            const float4 v4 = *(const float4*)&Wu[(size_t)(c0 + c)*Ev + k0 + k];
            Bs[k][c] = v4.x; Bs[k+1][c] = v4.y; Bs[k+2][c] = v4.z; Bs[k+3][c] = v4.w;
        }
        __syncthreads();

        #pragma unroll 8
        for (int k = 0; k < 32; k++) {
            const float4 a4 = *(const float4*)&As[k][ty*4];
            const float2 b2 = *(const float2*)&Bs[k][tx*2];
            const float a[4] = {a4.x, a4.y, a4.z, a4.w};
            #pragma unroll
            for (int ry = 0; ry < 4; ry++) {
                acc[ry][0] = fmaf(a[ry], b2.x, acc[ry][0]);
                acc[ry][1] = fmaf(a[ry], b2.y, acc[ry][1]);
            }
        }
    }

    const float2 bias = *(const float2*)&bu[c0 + tx*2];
    #pragma unroll
    for (int ry = 0; ry < 4; ry++) {
        float2 o;
        o.x = acc[ry][0] + bias.x;
        o.y = acc[ry][1] + bias.y;
        *(float2*)&out[(size_t)(r0 + ty*4 + ry)*Ev + c0 + tx*2] = o;
    }
}

// ---------------------------------------------------------------------------
extern "C" void kernel_launch(void* const* d_in, const int* in_sizes, int n_in,
                              void* d_out, int out_size)
{
    const float* x   = (const float*)d_in[0];
    const float* rk  = (const float*)d_in[1];
    const float* rv  = (const float*)d_in[2];
    const int*   msk = (const int*)  d_in[3];
    const float* Wq  = (const float*)d_in[4];
    const float* Wk  = (const float*)d_in[5];
    const float* Wv  = (const float*)d_in[6];
    const float* Wu  = (const float*)d_in[7];
    const float* bu  = (const float*)d_in[8];
    float* out = (float*)d_out;

    qkv_kernel<<<Bv*Tv, 256>>>(x, Wq, Wk, Wv);
    scc_kernel<<<dim3(4, 4, Bv*Hv), 256>>>();
    attn_kernel<<<Bv*Tv, 256>>>(rk, rv, msk);
    pv_kernel<<<dim3(4, Bv*Hv), 256>>>();
    proj_kernel<<<dim3(32, 16), 128>>>(Wu, bu, out);
}

// round 6
// speedup vs baseline: 1.1629x; 1.1629x over previous
#include <cuda_runtime.h>

#define Bv 4
#define Tv 256
#define Ev 512
#define Hv 8
#define Sv 64

typedef unsigned long long u64;

// packed fp32x2 helpers (FFMA2 path — ptxas never emits this from C++)
__device__ __forceinline__ u64 pk2(float x, float y) {
    u64 r; asm("mov.b64 %0,{%1,%2};" : "=l"(r) : "f"(x), "f"(y)); return r;
}
__device__ __forceinline__ void upk2(u64 v, float& x, float& y) {
    asm("mov.b64 {%0,%1},%2;" : "=f"(x), "=f"(y) : "l"(v));
}
__device__ __forceinline__ void fma2(u64& d, u64 a, u64 b) {
    asm("fma.rn.f32x2 %0,%1,%2,%0;" : "+l"(d) : "l"(a), "l"(b));
}
__device__ __forceinline__ u64 add2(u64 a, u64 b) {
    u64 r; asm("add.rn.f32x2 %0,%1,%2;" : "=l"(r) : "l"(a), "l"(b)); return r;
}

// scratch (allocation-free rule: __device__ globals)
__device__ float g_q[Bv*Tv*Ev];
__device__ float g_k[Bv*Tv*Ev];
__device__ float g_v[Bv*Tv*Ev];
__device__ float g_scc[Bv*Hv*Tv*Tv];   // [b][n][i][j]
__device__ float g_vec[Bv*Tv*Ev];

// ---------------------------------------------------------------------------
// K1: per-token q/k/v projections.
// ---------------------------------------------------------------------------
__global__ void __launch_bounds__(256) qkv_kernel(const float* __restrict__ x,
                                                  const float* __restrict__ Wq,
                                                  const float* __restrict__ Wk,
                                                  const float* __restrict__ Wv)
{
    __shared__ float Ws[64][65];
    __shared__ float xs[Ev];
    const int bt  = blockIdx.x;
    const int tid = threadIdx.x;

    xs[tid]       = x[(size_t)bt*Ev + tid];
    xs[tid + 256] = x[(size_t)bt*Ev + tid + 256];

    const float* Wlist[3] = {Wq, Wk, Wv};
    float*       Olist[3] = {g_q, g_k, g_v};

    #pragma unroll
    for (int w = 0; w < 3; w++) {
        __syncthreads();
        const float* W = Wlist[w];
        for (int idx = tid; idx < 64*64; idx += 256)
            Ws[idx >> 6][idx & 63] = W[idx];
        __syncthreads();

        const int e0 = 2 * tid;
        const int n  = e0 >> 6;
        const int o0 = e0 & 63;
        const float* xr = &xs[n * 64];
        u64 acc = pk2(0.f, 0.f);
        #pragma unroll
        for (int d = 0; d < 64; d++) {
            const float xv = xr[d];
            fma2(acc, pk2(xv, xv), pk2(Ws[o0][d], Ws[o0 + 1][d]));
        }
        float a0, a1; upk2(acc, a0, a1);
        Olist[w][(size_t)bt*Ev + e0]     = a0;
        Olist[w][(size_t)bt*Ev + e0 + 1] = a1;
    }
}

// ---------------------------------------------------------------------------
// K2: content-content scores  scc[b][n][i][j] = sum_d q[b,i,n,d]*k[b,j,n,d]
// K-major padded smem (LDS.128) + packed f32x2 FMA inner loop.
// ---------------------------------------------------------------------------
__global__ void __launch_bounds__(256) scc_kernel()
{
    __shared__ float qs[64][68];   // [d][i-row]
    __shared__ float ks[64][68];   // [d][j-row]
    const int it = blockIdx.x * 64;
    const int jt = blockIdx.y * 64;
    const int b  = blockIdx.z >> 3;
    const int n  = blockIdx.z & 7;
    const int tid = threadIdx.x;

    // vectorized gmem read (contiguous d), transposed smem store
    #pragma unroll
    for (int ch = tid; ch < 1024; ch += 256) {           // 1024 float4 chunks
        const int r = ch >> 4, d = (ch & 15) * 4;
        const float4 q4 = *(const float4*)&g_q[(((size_t)b*Tv + it + r)*Hv + n)*Sv + d];
        qs[d][r] = q4.x; qs[d+1][r] = q4.y; qs[d+2][r] = q4.z; qs[d+3][r] = q4.w;
        const float4 k4 = *(const float4*)&g_k[(((size_t)b*Tv + jt + r)*Hv + n)*Sv + d];
        ks[d][r] = k4.x; ks[d+1][r] = k4.y; ks[d+2][r] = k4.z; ks[d+3][r] = k4.w;
    }
    __syncthreads();

    const int ty = tid >> 4, tx = tid & 15;
    u64 accp[4][2];
    #pragma unroll
    for (int r = 0; r < 4; r++) { accp[r][0] = pk2(0.f,0.f); accp[r][1] = pk2(0.f,0.f); }

    #pragma unroll 8
    for (int d = 0; d < 64; d++) {
        const float4 a4 = *(const float4*)&qs[d][ty*4];
        const float4 c4 = *(const float4*)&ks[d][tx*4];
        const u64 c01 = pk2(c4.x, c4.y), c23 = pk2(c4.z, c4.w);
        const float a[4] = {a4.x, a4.y, a4.z, a4.w};
        #pragma unroll
        for (int r = 0; r < 4; r++) {
            const u64 aa = pk2(a[r], a[r]);
            fma2(accp[r][0], aa, c01);
            fma2(accp[r][1], aa, c23);
        }
    }

    #pragma unroll
    for (int r = 0; r < 4; r++) {
        float4 o;
        upk2(accp[r][0], o.x, o.y);
        upk2(accp[r][1], o.z, o.w);
        *(float4*)&g_scc[(((size_t)b*Hv + n)*Tv + it + ty*4 + r)*Tv + jt + tx*4] = o;
    }
}

// ---------------------------------------------------------------------------
// K3: streaming attention (R4 structure; Pass B uses packed f32x2).
// ---------------------------------------------------------------------------
__global__ void __launch_bounds__(256) attn_kernel(const float* __restrict__ ek,
                                                   const float* __restrict__ ev,
                                                   const int*   __restrict__ mask)
{
    __shared__ float sc[Hv][Tv];     // scores -> probs
    __shared__ float qsm[Ev];

    const int bi   = blockIdx.x;
    const int b    = bi >> 8;
    const int i    = bi & 255;
    const int tid  = threadIdx.x;
    const int warp = tid >> 5;
    const int lane = tid & 31;

    qsm[tid]       = g_q[(size_t)bi*Ev + tid];
    qsm[tid + 256] = g_q[(size_t)bi*Ev + tid + 256];

    // preload content-content scores: sc[n][j]
    #pragma unroll
    for (int t = 0; t < 8; t++)
        sc[t][tid] = g_scc[(((size_t)b*Hv + t)*Tv + i)*Tv + tid];
    __syncthreads();

    const float q0 = qsm[warp*64 + 2*lane];
    const float q1 = qsm[warp*64 + 2*lane + 1];

    const float2* ekp = (const float2*)ek + (((size_t)bi*Tv*Ev) >> 1) + warp*32 + lane;

    // ---- Pass A: stream ek, add q.ek to scores ----
    for (int j0 = 0; j0 < Tv; j0 += 8) {
        float2 r[8];
        #pragma unroll
        for (int u = 0; u < 8; u++) r[u] = ekp[(size_t)(j0 + u) * 256];
        #pragma unroll
        for (int u = 0; u < 8; u++) {
            float p = fmaf(r[u].x, q0, r[u].y * q1);
            p += __shfl_xor_sync(0xffffffffu, p, 16);
            p += __shfl_xor_sync(0xffffffffu, p, 8);
            p += __shfl_xor_sync(0xffffffffu, p, 4);
            p += __shfl_xor_sync(0xffffffffu, p, 2);
            p += __shfl_xor_sync(0xffffffffu, p, 1);
            if (lane == 0) sc[warp][j0 + u] += p;
        }
    }
    __syncwarp();

    // ---- softmax per head (warp-local over 256 j) ----
    const float scale = 0.125f;   // 1/sqrt(64)
    const int* mrow = mask + (size_t)bi * Tv;
    float vbuf[8];
    float mx = -1e30f;
    #pragma unroll
    for (int t = 0; t < 8; t++) {
        const int j = lane + 32*t;
        float s = sc[warp][j];
        s = (mrow[j] == 0) ? -1e9f : s * scale;
        vbuf[t] = s;
        mx = fmaxf(mx, s);
    }
    mx = fmaxf(mx, __shfl_xor_sync(0xffffffffu, mx, 16));
    mx = fmaxf(mx, __shfl_xor_sync(0xffffffffu, mx, 8));
    mx = fmaxf(mx, __shfl_xor_sync(0xffffffffu, mx, 4));
    mx = fmaxf(mx, __shfl_xor_sync(0xffffffffu, mx, 2));
    mx = fmaxf(mx, __shfl_xor_sync(0xffffffffu, mx, 1));
    float sum = 0.f;
    #pragma unroll
    for (int t = 0; t < 8; t++) {
        const float e = expf(vbuf[t] - mx);
        vbuf[t] = e;
        sum += e;
    }
    sum += __shfl_xor_sync(0xffffffffu, sum, 16);
    sum += __shfl_xor_sync(0xffffffffu, sum, 8);
    sum += __shfl_xor_sync(0xffffffffu, sum, 4);
    sum += __shfl_xor_sync(0xffffffffu, sum, 2);
    sum += __shfl_xor_sync(0xffffffffu, sum, 1);
    const float inv = 1.f / sum;
    #pragma unroll
    for (int t = 0; t < 8; t++)
        sc[warp][lane + 32*t] = vbuf[t] * inv;
    __syncwarp();

    // ---- Pass B: stream ev + L2-hit v, packed accumulate ----
    const float2* evp = (const float2*)ev  + (((size_t)bi*Tv*Ev) >> 1) + warp*32 + lane;
    const float2* vp  = (const float2*)g_v + (((size_t)b *Tv*Ev) >> 1) + warp*32 + lane;
    u64 acc = pk2(0.f, 0.f);
    for (int j0 = 0; j0 < Tv; j0 += 8) {
        float2 re[8], rv[8];
        #pragma unroll
        for (int u = 0; u < 8; u++) re[u] = evp[(size_t)(j0 + u) * 256];
        #pragma unroll
        for (int u = 0; u < 8; u++) rv[u] = vp[(size_t)(j0 + u) * 256];
        #pragma unroll
        for (int u = 0; u < 8; u++) {
            const float p = sc[warp][j0 + u];
            const u64 s = add2(pk2(re[u].x, re[u].y), pk2(rv[u].x, rv[u].y));
            fma2(acc, pk2(p, p), s);
        }
    }
    float a0, a1; upk2(acc, a0, a1);
    g_vec[(size_t)bi*Ev + warp*64 + 2*lane]     = a0;
    g_vec[(size_t)bi*Ev + warp*64 + 2*lane + 1] = a1;
}

// ---------------------------------------------------------------------------
// K4: out = vec @ Wu^T + bu.  BM=64, BN=32, BK=32, 128 threads, 256 CTAs.
// Packed f32x2 inner loop (8 FFMA2 + 4 packs per k vs 16 FFMA).
// ---------------------------------------------------------------------------
__global__ void __launch_bounds__(128) proj_kernel(const float* __restrict__ Wu,
                                                   const float* __restrict__ bu,
                                                   float* __restrict__ out)
{
    __shared__ float As[32][68];   // [k][r]  r0..r0+63
    __shared__ float Bs[32][36];   // [k][c]  c0..c0+31
    const int r0  = blockIdx.x * 64;
    const int c0  = blockIdx.y * 32;
    const int tid = threadIdx.x;
    const int ty  = tid >> 3;       // 0..15 -> rows ty*4..ty*4+3
    const int tx  = tid & 7;        // 0..7  -> cols tx*4..tx*4+3

    u64 accp[4][2];
    #pragma unroll
    for (int r = 0; r < 4; r++) { accp[r][0] = pk2(0.f,0.f); accp[r][1] = pk2(0.f,0.f); }

    for (int k0 = 0; k0 < Ev; k0 += 32) {
        __syncthreads();
        #pragma unroll
        for (int ch = tid; ch < 512; ch += 128) {
            const int r = ch >> 3, k = (ch & 7) * 4;
            const float4 v4 = *(const float4*)&g_vec[(size_t)(r0 + r)*Ev + k0 + k];
            As[k][r] = v4.x; As[k+1][r] = v4.y; As[k+2][r] = v4.z; As[k+3][r] = v4.w;
        }
        #pragma unroll
        for (int ch = tid; ch < 256; ch += 128) {
            const int c = ch >> 3, k = (ch & 7) * 4;
            const float4 v4 = *(const float4*)&Wu[(size_t)(c0 + c)*Ev + k0 + k];
            Bs[k][c] = v4.x; Bs[k+1][c] = v4.y; Bs[k+2][c] = v4.z; Bs[k+3][c] = v4.w;
        }
        __syncthreads();

        #pragma unroll 8
        for (int k = 0; k < 32; k++) {
            const float4 a4 = *(const float4*)&As[k][ty*4];
            const float4 b4 = *(const float4*)&Bs[k][tx*4];
            const u64 b01 = pk2(b4.x, b4.y), b23 = pk2(b4.z, b4.w);
            const float a[4] = {a4.x, a4.y, a4.z, a4.w};
            #pragma unroll
            for (int ry = 0; ry < 4; ry++) {
                const u64 aa = pk2(a[ry], a[ry]);
                fma2(accp[ry][0], aa, b01);
                fma2(accp[ry][1], aa, b23);
            }
        }
    }

    const float4 bias = *(const float4*)&bu[c0 + tx*4];
    #pragma unroll
    for (int ry = 0; ry < 4; ry++) {
        float4 o;
        upk2(accp[ry][0], o.x, o.y);
        upk2(accp[ry][1], o.z, o.w);
        o.x += bias.x; o.y += bias.y; o.z += bias.z; o.w += bias.w;
        *(float4*)&out[(size_t)(r0 + ty*4 + ry)*Ev + c0 + tx*4] = o;
    }
}

// ---------------------------------------------------------------------------
extern "C" void kernel_launch(void* const* d_in, const int* in_sizes, int n_in,
                              void* d_out, int out_size)
{
    const float* x   = (const float*)d_in[0];
    const float* rk  = (const float*)d_in[1];
    const float* rv  = (const float*)d_in[2];
    const int*   msk = (const int*)  d_in[3];
    const float* Wq  = (const float*)d_in[4];
    const float* Wk  = (const float*)d_in[5];
    const float* Wv  = (const float*)d_in[6];
    const float* Wu  = (const float*)d_in[7];
    const float* bu  = (const float*)d_in[8];
    float* out = (float*)d_out;

    qkv_kernel<<<Bv*Tv, 256>>>(x, Wq, Wk, Wv);
    scc_kernel<<<dim3(4, 4, Bv*Hv), 256>>>();
    attn_kernel<<<Bv*Tv, 256>>>(rk, rv, msk);
    proj_kernel<<<dim3(16, 16), 128>>>(Wu, bu, out);
}

// round 7
// speedup vs baseline: 1.1703x; 1.0064x over previous
#include <cuda_runtime.h>

#define Bv 4
#define Tv 256
#define Ev 512
#define Hv 8
#define Sv 64

typedef unsigned long long u64;

// packed fp32x2 helpers (FFMA2 path — ptxas never emits this from C++)
__device__ __forceinline__ u64 pk2(float x, float y) {
    u64 r; asm("mov.b64 %0,{%1,%2};" : "=l"(r) : "f"(x), "f"(y)); return r;
}
__device__ __forceinline__ void upk2(u64 v, float& x, float& y) {
    asm("mov.b64 {%0,%1},%2;" : "=f"(x), "=f"(y) : "l"(v));
}
__device__ __forceinline__ void fma2(u64& d, u64 a, u64 b) {
    asm("fma.rn.f32x2 %0,%1,%2,%0;" : "+l"(d) : "l"(a), "l"(b));
}
__device__ __forceinline__ u64 add2(u64 a, u64 b) {
    u64 r; asm("add.rn.f32x2 %0,%1,%2;" : "=l"(r) : "l"(a), "l"(b)); return r;
}

// scratch (allocation-free rule: __device__ globals)
__device__ float g_q[Bv*Tv*Ev];
__device__ float g_k[Bv*Tv*Ev];
__device__ float g_v[Bv*Tv*Ev];
__device__ float g_vec[Bv*Tv*Ev];

// ---------------------------------------------------------------------------
// K1: per-token q/k/v projections.
// ---------------------------------------------------------------------------
__global__ void __launch_bounds__(256) qkv_kernel(const float* __restrict__ x,
                                                  const float* __restrict__ Wq,
                                                  const float* __restrict__ Wk,
                                                  const float* __restrict__ Wv)
{
    __shared__ float Ws[64][65];
    __shared__ float xs[Ev];
    const int bt  = blockIdx.x;
    const int tid = threadIdx.x;

    xs[tid]       = x[(size_t)bt*Ev + tid];
    xs[tid + 256] = x[(size_t)bt*Ev + tid + 256];

    const float* Wlist[3] = {Wq, Wk, Wv};
    float*       Olist[3] = {g_q, g_k, g_v};

    #pragma unroll
    for (int w = 0; w < 3; w++) {
        __syncthreads();
        const float* W = Wlist[w];
        for (int idx = tid; idx < 64*64; idx += 256)
            Ws[idx >> 6][idx & 63] = W[idx];
        __syncthreads();

        const int e0 = 2 * tid;
        const int n  = e0 >> 6;
        const int o0 = e0 & 63;
        const float* xr = &xs[n * 64];
        u64 acc = pk2(0.f, 0.f);
        #pragma unroll
        for (int d = 0; d < 64; d++) {
            const float xv = xr[d];
            fma2(acc, pk2(xv, xv), pk2(Ws[o0][d], Ws[o0 + 1][d]));
        }
        float a0, a1; upk2(acc, a0, a1);
        Olist[w][(size_t)bt*Ev + e0]     = a0;
        Olist[w][(size_t)bt*Ev + e0 + 1] = a1;
    }
}

// ---------------------------------------------------------------------------
// K2: fused attention. One CTA per (b,i); warp n = head n.
// Pass A: score[n][j] = q . (k[j] + ek[i,j])   (k from L2, ek streamed)
// softmax, Pass B: vec = sum_j prob * (v[j] + ev[i,j])
// ---------------------------------------------------------------------------
__global__ void __launch_bounds__(256) attn_kernel(const float* __restrict__ ek,
                                                   const float* __restrict__ ev,
                                                   const int*   __restrict__ mask)
{
    __shared__ float sc[Hv][Tv];     // scores -> probs
    __shared__ float qsm[Ev];

    const int bi   = blockIdx.x;
    const int b    = bi >> 8;
    const int tid  = threadIdx.x;
    const int warp = tid >> 5;
    const int lane = tid & 31;

    qsm[tid]       = g_q[(size_t)bi*Ev + tid];
    qsm[tid + 256] = g_q[(size_t)bi*Ev + tid + 256];
    __syncthreads();

    const float q0 = qsm[warp*64 + 2*lane];
    const float q1 = qsm[warp*64 + 2*lane + 1];

    const float2* ekp = (const float2*)ek  + (((size_t)bi*Tv*Ev) >> 1) + warp*32 + lane;
    const float2* kp  = (const float2*)g_k + (((size_t)b *Tv*Ev) >> 1) + warp*32 + lane;

    // ---- Pass A: score = q.(k + ek), single shuffle tree ----
    for (int j0 = 0; j0 < Tv; j0 += 8) {
        float2 re[8], rk[8];
        #pragma unroll
        for (int u = 0; u < 8; u++) re[u] = ekp[(size_t)(j0 + u) * 256];
        #pragma unroll
        for (int u = 0; u < 8; u++) rk[u] = kp[(size_t)(j0 + u) * 256];
        #pragma unroll
        for (int u = 0; u < 8; u++) {
            const float sx = re[u].x + rk[u].x;
            const float sy = re[u].y + rk[u].y;
            float p = fmaf(sx, q0, sy * q1);
            p += __shfl_xor_sync(0xffffffffu, p, 16);
            p += __shfl_xor_sync(0xffffffffu, p, 8);
            p += __shfl_xor_sync(0xffffffffu, p, 4);
            p += __shfl_xor_sync(0xffffffffu, p, 2);
            p += __shfl_xor_sync(0xffffffffu, p, 1);
            if (lane == 0) sc[warp][j0 + u] = p;
        }
    }
    __syncwarp();

    // ---- softmax per head (warp-local over 256 j) ----
    const float scale = 0.125f;   // 1/sqrt(64)
    const int* mrow = mask + (size_t)bi * Tv;
    float vbuf[8];
    float mx = -1e30f;
    #pragma unroll
    for (int t = 0; t < 8; t++) {
        const int j = lane + 32*t;
        float s = sc[warp][j];
        s = (mrow[j] == 0) ? -1e9f : s * scale;
        vbuf[t] = s;
        mx = fmaxf(mx, s);
    }
    mx = fmaxf(mx, __shfl_xor_sync(0xffffffffu, mx, 16));
    mx = fmaxf(mx, __shfl_xor_sync(0xffffffffu, mx, 8));
    mx = fmaxf(mx, __shfl_xor_sync(0xffffffffu, mx, 4));
    mx = fmaxf(mx, __shfl_xor_sync(0xffffffffu, mx, 2));
    mx = fmaxf(mx, __shfl_xor_sync(0xffffffffu, mx, 1));
    float sum = 0.f;
    #pragma unroll
    for (int t = 0; t < 8; t++) {
        const float e = expf(vbuf[t] - mx);
        vbuf[t] = e;
        sum += e;
    }
    sum += __shfl_xor_sync(0xffffffffu, sum, 16);
    sum += __shfl_xor_sync(0xffffffffu, sum, 8);
    sum += __shfl_xor_sync(0xffffffffu, sum, 4);
    sum += __shfl_xor_sync(0xffffffffu, sum, 2);
    sum += __shfl_xor_sync(0xffffffffu, sum, 1);
    const float inv = 1.f / sum;
    #pragma unroll
    for (int t = 0; t < 8; t++)
        sc[warp][lane + 32*t] = vbuf[t] * inv;
    __syncwarp();

    // ---- Pass B: vec = sum_j prob*(v + ev), packed ----
    const float2* evp = (const float2*)ev  + (((size_t)bi*Tv*Ev) >> 1) + warp*32 + lane;
    const float2* vp  = (const float2*)g_v + (((size_t)b *Tv*Ev) >> 1) + warp*32 + lane;
    u64 acc = pk2(0.f, 0.f);
    for (int j0 = 0; j0 < Tv; j0 += 8) {
        float2 re[8], rv[8];
        #pragma unroll
        for (int u = 0; u < 8; u++) re[u] = evp[(size_t)(j0 + u) * 256];
        #pragma unroll
        for (int u = 0; u < 8; u++) rv[u] = vp[(size_t)(j0 + u) * 256];
        #pragma unroll
        for (int u = 0; u < 8; u++) {
            const float p = sc[warp][j0 + u];
            const u64 s = add2(pk2(re[u].x, re[u].y), pk2(rv[u].x, rv[u].y));
            fma2(acc, pk2(p, p), s);
        }
    }
    float a0, a1; upk2(acc, a0, a1);
    g_vec[(size_t)bi*Ev + warp*64 + 2*lane]     = a0;
    g_vec[(size_t)bi*Ev + warp*64 + 2*lane + 1] = a1;
}

// ---------------------------------------------------------------------------
// K3: out = vec @ Wu^T + bu.  BM=32, BN=32, BK=32, 128 threads.
// grid = (32,16) = 512 CTAs -> ~3.5 CTAs/SM, FFMA2 inner loop.
// ---------------------------------------------------------------------------
__global__ void __launch_bounds__(128) proj_kernel(const float* __restrict__ Wu,
                                                   const float* __restrict__ bu,
                                                   float* __restrict__ out)
{
    __shared__ float As[32][36];   // [k][r]
    __shared__ float Bs[32][36];   // [k][c]
    const int r0  = blockIdx.x * 32;
    const int c0  = blockIdx.y * 32;
    const int tid = threadIdx.x;
    const int ty  = tid >> 4;       // 0..7  -> rows ty*4..+3
    const int tx  = tid & 15;       // 0..15 -> cols tx*2..+1

    u64 accp[4];
    #pragma unroll
    for (int r = 0; r < 4; r++) accp[r] = pk2(0.f, 0.f);

    for (int k0 = 0; k0 < Ev; k0 += 32) {
        __syncthreads();
        #pragma unroll
        for (int ch = tid; ch < 256; ch += 128) {
            const int r = ch >> 3, k = (ch & 7) * 4;
            const float4 v4 = *(const float4*)&g_vec[(size_t)(r0 + r)*Ev + k0 + k];
            As[k][r] = v4.x; As[k+1][r] = v4.y; As[k+2][r] = v4.z; As[k+3][r] = v4.w;
        }
        #pragma unroll
        for (int ch = tid; ch < 256; ch += 128) {
            const int c = ch >> 3, k = (ch & 7) * 4;
            const float4 v4 = *(const float4*)&Wu[(size_t)(c0 + c)*Ev + k0 + k];
            Bs[k][c] = v4.x; Bs[k+1][c] = v4.y; Bs[k+2][c] = v4.z; Bs[k+3][c] = v4.w;
        }
        __syncthreads();

        #pragma unroll 8
        for (int k = 0; k < 32; k++) {
            const float4 a4 = *(const float4*)&As[k][ty*4];
            const float2 b2 = *(const float2*)&Bs[k][tx*2];
            const u64 bb = pk2(b2.x, b2.y);
            const float a[4] = {a4.x, a4.y, a4.z, a4.w};
            #pragma unroll
            for (int ry = 0; ry < 4; ry++)
                fma2(accp[ry], pk2(a[ry], a[ry]), bb);
        }
    }

    const float2 bias = *(const float2*)&bu[c0 + tx*2];
    #pragma unroll
    for (int ry = 0; ry < 4; ry++) {
        float2 o;
        upk2(accp[ry], o.x, o.y);
        o.x += bias.x; o.y += bias.y;
        *(float2*)&out[(size_t)(r0 + ty*4 + ry)*Ev + c0 + tx*2] = o;
    }
}

// ---------------------------------------------------------------------------
extern "C" void kernel_launch(void* const* d_in, const int* in_sizes, int n_in,
                              void* d_out, int out_size)
{
    const float* x   = (const float*)d_in[0];
    const float* rk  = (const float*)d_in[1];
    const float* rv  = (const float*)d_in[2];
    const int*   msk = (const int*)  d_in[3];
    const float* Wq  = (const float*)d_in[4];
    const float* Wk  = (const float*)d_in[5];
    const float* Wv  = (const float*)d_in[6];
    const float* Wu  = (const float*)d_in[7];
    const float* bu  = (const float*)d_in[8];
    float* out = (float*)d_out;

    qkv_kernel<<<Bv*Tv, 256>>>(x, Wq, Wk, Wv);
    attn_kernel<<<Bv*Tv, 256>>>(rk, rv, msk);
    proj_kernel<<<dim3(32, 16), 128>>>(Wu, bu, out);
}

// round 8
// speedup vs baseline: 1.2202x; 1.0426x over previous
#include <cuda_runtime.h>

#define Bv 4
#define Tv 256
#define Ev 512
#define Hv 8
#define Sv 64

typedef unsigned long long u64;

// packed fp32x2 helpers (FFMA2 path — ptxas never emits this from C++)
__device__ __forceinline__ u64 pk2(float x, float y) {
    u64 r; asm("mov.b64 %0,{%1,%2};" : "=l"(r) : "f"(x), "f"(y)); return r;
}
__device__ __forceinline__ void upk2(u64 v, float& x, float& y) {
    asm("mov.b64 {%0,%1},%2;" : "=f"(x), "=f"(y) : "l"(v));
}
__device__ __forceinline__ void fma2(u64& d, u64 a, u64 b) {
    asm("fma.rn.f32x2 %0,%1,%2,%0;" : "+l"(d) : "l"(a), "l"(b));
}
__device__ __forceinline__ u64 add2(u64 a, u64 b) {
    u64 r; asm("add.rn.f32x2 %0,%1,%2;" : "=l"(r) : "l"(a), "l"(b)); return r;
}

// scratch (allocation-free rule: __device__ globals)
__device__ float g_q[Bv*Tv*Ev];
__device__ float g_k[Bv*Tv*Ev];
__device__ float g_v[Bv*Tv*Ev];
__device__ float g_vec[Bv*Tv*Ev];

// ---------------------------------------------------------------------------
// K1: q/k/v projections as a tiled GEMM.
// grid = (16 token-tiles, 8 heads), 256 threads.
// x tile [64 tok][64 d] loaded once (K-major smem), reused for Wq/Wk/Wv.
// ---------------------------------------------------------------------------
__global__ void __launch_bounds__(256) qkv_kernel(const float* __restrict__ x,
                                                  const float* __restrict__ Wq,
                                                  const float* __restrict__ Wk,
                                                  const float* __restrict__ Wv)
{
    __shared__ float xs[64][68];   // [d][token]
    __shared__ float ws[64][68];   // [d][o]
    const int t0  = blockIdx.x * 64;
    const int n   = blockIdx.y;
    const int tid = threadIdx.x;
    const int ty  = tid >> 4, tx = tid & 15;

    // load x tile (coalesced on d, transposed store)
    #pragma unroll
    for (int ch = tid; ch < 1024; ch += 256) {
        const int r = ch >> 4, d = (ch & 15) * 4;
        const float4 v4 = *(const float4*)&x[(size_t)(t0 + r)*Ev + n*Sv + d];
        xs[d][r] = v4.x; xs[d+1][r] = v4.y; xs[d+2][r] = v4.z; xs[d+3][r] = v4.w;
    }

    const float* Wlist[3] = {Wq, Wk, Wv};
    float*       Olist[3] = {g_q, g_k, g_v};

    #pragma unroll
    for (int w = 0; w < 3; w++) {
        __syncthreads();     // (w=0: x tile done; w>0: ws consumers done)
        const float* W = Wlist[w];
        #pragma unroll
        for (int ch = tid; ch < 1024; ch += 256) {
            const int o = ch >> 4, d = (ch & 15) * 4;
            const float4 v4 = *(const float4*)&W[o*Sv + d];
            ws[d][o] = v4.x; ws[d+1][o] = v4.y; ws[d+2][o] = v4.z; ws[d+3][o] = v4.w;
        }
        __syncthreads();

        u64 accp[4][2];
        #pragma unroll
        for (int r = 0; r < 4; r++) { accp[r][0] = pk2(0.f,0.f); accp[r][1] = pk2(0.f,0.f); }

        #pragma unroll 8
        for (int k = 0; k < 64; k++) {
            const float4 a4 = *(const float4*)&xs[k][ty*4];
            const float4 b4 = *(const float4*)&ws[k][tx*4];
            const u64 b01 = pk2(b4.x, b4.y), b23 = pk2(b4.z, b4.w);
            const float a[4] = {a4.x, a4.y, a4.z, a4.w};
            #pragma unroll
            for (int r = 0; r < 4; r++) {
                const u64 aa = pk2(a[r], a[r]);
                fma2(accp[r][0], aa, b01);
                fma2(accp[r][1], aa, b23);
            }
        }

        float* O = Olist[w];
        #pragma unroll
        for (int r = 0; r < 4; r++) {
            float4 o;
            upk2(accp[r][0], o.x, o.y);
            upk2(accp[r][1], o.z, o.w);
            *(float4*)&O[(size_t)(t0 + ty*4 + r)*Ev + n*Sv + tx*4] = o;
        }
    }
}

// ---------------------------------------------------------------------------
// K2: fused attention. One CTA per (b,i); warp n = head n.
// Pass A: score[n][j] = q . (k[j] + ek[i,j])   (k from L2, ek streamed)
// softmax, Pass B: vec = sum_j prob * (v[j] + ev[i,j])
// ---------------------------------------------------------------------------
__global__ void __launch_bounds__(256) attn_kernel(const float* __restrict__ ek,
                                                   const float* __restrict__ ev,
                                                   const int*   __restrict__ mask)
{
    __shared__ float sc[Hv][Tv];     // scores -> probs
    __shared__ float qsm[Ev];

    const int bi   = blockIdx.x;
    const int b    = bi >> 8;
    const int tid  = threadIdx.x;
    const int warp = tid >> 5;
    const int lane = tid & 31;

    qsm[tid]       = g_q[(size_t)bi*Ev + tid];
    qsm[tid + 256] = g_q[(size_t)bi*Ev + tid + 256];
    __syncthreads();

    const float q0 = qsm[warp*64 + 2*lane];
    const float q1 = qsm[warp*64 + 2*lane + 1];

    const float2* ekp = (const float2*)ek  + (((size_t)bi*Tv*Ev) >> 1) + warp*32 + lane;
    const float2* kp  = (const float2*)g_k + (((size_t)b *Tv*Ev) >> 1) + warp*32 + lane;

    // ---- Pass A: score = q.(k + ek), single shuffle tree ----
    for (int j0 = 0; j0 < Tv; j0 += 8) {
        float2 re[8], rk[8];
        #pragma unroll
        for (int u = 0; u < 8; u++) re[u] = ekp[(size_t)(j0 + u) * 256];
        #pragma unroll
        for (int u = 0; u < 8; u++) rk[u] = kp[(size_t)(j0 + u) * 256];
        #pragma unroll
        for (int u = 0; u < 8; u++) {
            const float sx = re[u].x + rk[u].x;
            const float sy = re[u].y + rk[u].y;
            float p = fmaf(sx, q0, sy * q1);
            p += __shfl_xor_sync(0xffffffffu, p, 16);
            p += __shfl_xor_sync(0xffffffffu, p, 8);
            p += __shfl_xor_sync(0xffffffffu, p, 4);
            p += __shfl_xor_sync(0xffffffffu, p, 2);
            p += __shfl_xor_sync(0xffffffffu, p, 1);
            if (lane == 0) sc[warp][j0 + u] = p;
        }
    }
    __syncwarp();

    // ---- softmax per head (warp-local over 256 j) ----
    const float scale = 0.125f;   // 1/sqrt(64)
    const int* mrow = mask + (size_t)bi * Tv;
    float vbuf[8];
    float mx = -1e30f;
    #pragma unroll
    for (int t = 0; t < 8; t++) {
        const int j = lane + 32*t;
        float s = sc[warp][j];
        s = (mrow[j] == 0) ? -1e9f : s * scale;
        vbuf[t] = s;
        mx = fmaxf(mx, s);
    }
    mx = fmaxf(mx, __shfl_xor_sync(0xffffffffu, mx, 16));
    mx = fmaxf(mx, __shfl_xor_sync(0xffffffffu, mx, 8));
    mx = fmaxf(mx, __shfl_xor_sync(0xffffffffu, mx, 4));
    mx = fmaxf(mx, __shfl_xor_sync(0xffffffffu, mx, 2));
    mx = fmaxf(mx, __shfl_xor_sync(0xffffffffu, mx, 1));
    float sum = 0.f;
    #pragma unroll
    for (int t = 0; t < 8; t++) {
        const float e = expf(vbuf[t] - mx);
        vbuf[t] = e;
        sum += e;
    }
    sum += __shfl_xor_sync(0xffffffffu, sum, 16);
    sum += __shfl_xor_sync(0xffffffffu, sum, 8);
    sum += __shfl_xor_sync(0xffffffffu, sum, 4);
    sum += __shfl_xor_sync(0xffffffffu, sum, 2);
    sum += __shfl_xor_sync(0xffffffffu, sum, 1);
    const float inv = 1.f / sum;
    #pragma unroll
    for (int t = 0; t < 8; t++)
        sc[warp][lane + 32*t] = vbuf[t] * inv;
    __syncwarp();

    // ---- Pass B: vec = sum_j prob*(v + ev), packed ----
    const float2* evp = (const float2*)ev  + (((size_t)bi*Tv*Ev) >> 1) + warp*32 + lane;
    const float2* vp  = (const float2*)g_v + (((size_t)b *Tv*Ev) >> 1) + warp*32 + lane;
    u64 acc = pk2(0.f, 0.f);
    for (int j0 = 0; j0 < Tv; j0 += 8) {
        float2 re[8], rv[8];
        #pragma unroll
        for (int u = 0; u < 8; u++) re[u] = evp[(size_t)(j0 + u) * 256];
        #pragma unroll
        for (int u = 0; u < 8; u++) rv[u] = vp[(size_t)(j0 + u) * 256];
        #pragma unroll
        for (int u = 0; u < 8; u++) {
            const float p = sc[warp][j0 + u];
            const u64 s = add2(pk2(re[u].x, re[u].y), pk2(rv[u].x, rv[u].y));
            fma2(acc, pk2(p, p), s);
        }
    }
    float a0, a1; upk2(acc, a0, a1);
    g_vec[(size_t)bi*Ev + warp*64 + 2*lane]     = a0;
    g_vec[(size_t)bi*Ev + warp*64 + 2*lane + 1] = a1;
}

// ---------------------------------------------------------------------------
// K3: out = vec @ Wu^T + bu.  BM=32, BN=32, BK=32, 128 threads.
// grid = (32,16) = 512 CTAs -> ~3.5 CTAs/SM, FFMA2 inner loop.
// ---------------------------------------------------------------------------
__global__ void __launch_bounds__(128) proj_kernel(const float* __restrict__ Wu,
                                                   const float* __restrict__ bu,
                                                   float* __restrict__ out)
{
    __shared__ float As[32][36];   // [k][r]
    __shared__ float Bs[32][36];   // [k][c]
    const int r0  = blockIdx.x * 32;
    const int c0  = blockIdx.y * 32;
    const int tid = threadIdx.x;
    const int ty  = tid >> 4;       // 0..7  -> rows ty*4..+3
    const int tx  = tid & 15;       // 0..15 -> cols tx*2..+1

    u64 accp[4];
    #pragma unroll
    for (int r = 0; r < 4; r++) accp[r] = pk2(0.f, 0.f);

    for (int k0 = 0; k0 < Ev; k0 += 32) {
        __syncthreads();
        #pragma unroll
        for (int ch = tid; ch < 256; ch += 128) {
            const int r = ch >> 3, k = (ch & 7) * 4;
            const float4 v4 = *(const float4*)&g_vec[(size_t)(r0 + r)*Ev + k0 + k];
            As[k][r] = v4.x; As[k+1][r] = v4.y; As[k+2][r] = v4.z; As[k+3][r] = v4.w;
        }
        #pragma unroll
        for (int ch = tid; ch < 256; ch += 128) {
            const int c = ch >> 3, k = (ch & 7) * 4;
            const float4 v4 = *(const float4*)&Wu[(size_t)(c0 + c)*Ev + k0 + k];
            Bs[k][c] = v4.x; Bs[k+1][c] = v4.y; Bs[k+2][c] = v4.z; Bs[k+3][c] = v4.w;
        }
        __syncthreads();

        #pragma unroll 8
        for (int k = 0; k < 32; k++) {
            const float4 a4 = *(const float4*)&As[k][ty*4];
            const float2 b2 = *(const float2*)&Bs[k][tx*2];
            const u64 bb = pk2(b2.x, b2.y);
            const float a[4] = {a4.x, a4.y, a4.z, a4.w};
            #pragma unroll
            for (int ry = 0; ry < 4; ry++)
                fma2(accp[ry], pk2(a[ry], a[ry]), bb);
        }
    }

    const float2 bias = *(const float2*)&bu[c0 + tx*2];
    #pragma unroll
    for (int ry = 0; ry < 4; ry++) {
        float2 o;
        upk2(accp[ry], o.x, o.y);
        o.x += bias.x; o.y += bias.y;
        *(float2*)&out[(size_t)(r0 + ty*4 + ry)*Ev + c0 + tx*2] = o;
    }
}

// ---------------------------------------------------------------------------
extern "C" void kernel_launch(void* const* d_in, const int* in_sizes, int n_in,
                              void* d_out, int out_size)
{
    const float* x   = (const float*)d_in[0];
    const float* rk  = (const float*)d_in[1];
    const float* rv  = (const float*)d_in[2];
    const int*   msk = (const int*)  d_in[3];
    const float* Wq  = (const float*)d_in[4];
    const float* Wk  = (const float*)d_in[5];
    const float* Wv  = (const float*)d_in[6];
    const float* Wu  = (const float*)d_in[7];
    const float* bu  = (const float*)d_in[8];
    float* out = (float*)d_out;

    qkv_kernel<<<dim3(16, Hv), 256>>>(x, Wq, Wk, Wv);
    attn_kernel<<<Bv*Tv, 256>>>(rk, rv, msk);
    proj_kernel<<<dim3(32, 16), 128>>>(Wu, bu, out);
}